// round 2
// baseline (speedup 1.0000x reference)
#include <cuda_runtime.h>

#define NN 50000
#define EE 600000
#define HH 128
#define GG 64

// ---------------- static scratch (no allocations allowed) ----------------
__device__ __align__(16) float d_h0[NN * HH];
__device__ __align__(16) float d_h1[NN * HH];
__device__ __align__(16) float d_agg[NN * HH];
__device__ int   d_rowptr[3 * (NN + 1)];
__device__ int   d_cur[3 * NN];      // counts, then running offsets
__device__ int   d_ssrc[3 * EE];     // src ids sorted by dst
__device__ float d_invc[3 * NN];     // 1/max(cnt,1)
__device__ __align__(16) float d_g[GG * HH];

// ---------------- small utility kernels ----------------
__global__ void zero_int_kernel(int* __restrict__ p, int n) {
    int i = blockIdx.x * blockDim.x + threadIdx.x;
    if (i < n) p[i] = 0;
}
__global__ void zero_float_kernel(float* __restrict__ p, int n) {
    int i = blockIdx.x * blockDim.x + threadIdx.x;
    if (i < n) p[i] = 0.0f;
}

// ---------------- CSR build: histogram, scan, fill ----------------
__global__ void hist_kernel(const int* __restrict__ dst, int* __restrict__ cnt) {
    int e = blockIdx.x * blockDim.x + threadIdx.x;
    if (e < EE) atomicAdd(&cnt[dst[e]], 1);
}

// single block, 1024 threads: exclusive scan of counts -> rowptr, copy to cur,
// and invc = 1/max(cnt,1)
__global__ void scan_kernel(int* __restrict__ cntcur, int* __restrict__ rowptr,
                            float* __restrict__ invc) {
    __shared__ int wsum[32];
    __shared__ int sbase;
    int tid = threadIdx.x, lane = tid & 31, wid = tid >> 5;
    if (tid == 0) sbase = 0;
    __syncthreads();
    for (int start = 0; start < NN; start += 1024) {
        int i = start + tid;
        int v = (i < NN) ? cntcur[i] : 0;
        int xinc = v;
#pragma unroll
        for (int o = 1; o < 32; o <<= 1) {
            int y = __shfl_up_sync(0xffffffffu, xinc, o);
            if (lane >= o) xinc += y;
        }
        if (lane == 31) wsum[wid] = xinc;
        __syncthreads();
        if (wid == 0) {
            int wv = wsum[lane];
            int ws = wv;
#pragma unroll
            for (int o = 1; o < 32; o <<= 1) {
                int y = __shfl_up_sync(0xffffffffu, ws, o);
                if (lane >= o) ws += y;
            }
            wsum[lane] = ws - wv;
        }
        __syncthreads();
        int excl = xinc - v + wsum[wid] + sbase;
        if (i < NN) {
            rowptr[i] = excl;
            cntcur[i] = excl;
            invc[i]   = 1.0f / (float)((v > 0) ? v : 1);
        }
        __syncthreads();
        if (tid == 1023) sbase = excl + v;
        __syncthreads();
    }
    if (tid == 0) rowptr[NN] = sbase;
}

__global__ void fill_kernel(const int* __restrict__ src, const int* __restrict__ dst,
                            int* __restrict__ cur, int* __restrict__ ssrc) {
    int e = blockIdx.x * blockDim.x + threadIdx.x;
    if (e < EE) {
        int p = atomicAdd(&cur[dst[e]], 1);
        ssrc[p] = src[e];
    }
}

// ---------------- mean-aggregate: one warp per node (gather, no atomics) ----
__global__ void __launch_bounds__(256) gather_kernel(
    const float* __restrict__ xin, const int* __restrict__ rowptr,
    const int* __restrict__ ssrc, const float* __restrict__ invc,
    float* __restrict__ aggout) {
    int gw = (blockIdx.x * blockDim.x + threadIdx.x) >> 5;
    int lane = threadIdx.x & 31;
    if (gw >= NN) return;
    const float4* X = (const float4*)xin;
    int beg = rowptr[gw], end = rowptr[gw + 1];
    float4 acc = make_float4(0.f, 0.f, 0.f, 0.f);
    int e = beg;
    for (; e + 2 <= end; e += 2) {
        int s0 = ssrc[e], s1 = ssrc[e + 1];
        float4 v0 = X[s0 * 32 + lane];
        float4 v1 = X[s1 * 32 + lane];
        acc.x += v0.x + v1.x;
        acc.y += v0.y + v1.y;
        acc.z += v0.z + v1.z;
        acc.w += v0.w + v1.w;
    }
    if (e < end) {
        int s = ssrc[e];
        float4 v = X[s * 32 + lane];
        acc.x += v.x; acc.y += v.y; acc.z += v.z; acc.w += v.w;
    }
    float ic = invc[gw];
    float4 o = make_float4(acc.x * ic, acc.y * ic, acc.z * ic, acc.w * ic);
    ((float4*)aggout)[gw * 32 + lane] = o;
}

// ---------------- fused dual GEMM + bias + (optional) L2 row-norm ----------
// out[r, :] = agg[r, :] @ Wl + x[r, :] @ Wr + bl ; optional F.normalize
// block = 256 threads, tile = 128 rows x 128 cols, thread tile = 8x8
template <bool NORM>
__global__ void __launch_bounds__(256, 2) sage_gemm(
    const float* __restrict__ Agg, const float* __restrict__ Xin,
    const float* __restrict__ Wl, const float* __restrict__ Wr,
    const float* __restrict__ bias, float* __restrict__ outp) {
    __shared__ float Ws[16 * 128];   // W chunk, row-major [k][j]
    __shared__ float As[16 * 132];   // A chunk transposed [k][row], padded
    const int tid = threadIdx.x;
    const int tr = tid >> 4, tc = tid & 15;
    const int row0 = blockIdx.x * 128;

    float acc[8][8];
#pragma unroll
    for (int i = 0; i < 8; i++)
#pragma unroll
        for (int j = 0; j < 8; j++) acc[i][j] = 0.f;

    for (int kc = 0; kc < 16; kc++) {
        const float* A = (kc < 8) ? Agg : Xin;
        const float* W = (kc < 8) ? Wl : Wr;
        const int kb = (kc & 7) * 16;
        // stage W chunk: 16 rows x 128 cols
        {
            const float4* W4 = (const float4*)(W + kb * HH);
            float4* Ws4 = (float4*)Ws;
            Ws4[tid]       = W4[tid];
            Ws4[tid + 256] = W4[tid + 256];
        }
        // stage A chunk transposed
#pragma unroll
        for (int it = 0; it < 2; it++) {
            int fi = tid + it * 256;
            int r = fi >> 2, q = fi & 3;
            int grow = row0 + r;
            float4 v = make_float4(0.f, 0.f, 0.f, 0.f);
            if (grow < NN) v = ((const float4*)A)[grow * 32 + (kb >> 2) + q];
            As[(q * 4 + 0) * 132 + r] = v.x;
            As[(q * 4 + 1) * 132 + r] = v.y;
            As[(q * 4 + 2) * 132 + r] = v.z;
            As[(q * 4 + 3) * 132 + r] = v.w;
        }
        __syncthreads();
#pragma unroll
        for (int k = 0; k < 16; k++) {
            float4 a0 = *(const float4*)&As[k * 132 + tr * 8];
            float4 a1 = *(const float4*)&As[k * 132 + tr * 8 + 4];
            float4 b0 = *(const float4*)&Ws[k * 128 + tc * 4];
            float4 b1 = *(const float4*)&Ws[k * 128 + 64 + tc * 4];
            float a[8] = {a0.x, a0.y, a0.z, a0.w, a1.x, a1.y, a1.z, a1.w};
            float b[8] = {b0.x, b0.y, b0.z, b0.w, b1.x, b1.y, b1.z, b1.w};
#pragma unroll
            for (int i = 0; i < 8; i++)
#pragma unroll
                for (int j = 0; j < 8; j++)
                    acc[i][j] = fmaf(a[i], b[j], acc[i][j]);
        }
        __syncthreads();
    }

    // bias (cols: tc*4..tc*4+3 and 64+tc*4..64+tc*4+3)
    float4 bb0 = *(const float4*)&bias[tc * 4];
    float4 bb1 = *(const float4*)&bias[64 + tc * 4];
    float bj[8] = {bb0.x, bb0.y, bb0.z, bb0.w, bb1.x, bb1.y, bb1.z, bb1.w};
#pragma unroll
    for (int i = 0; i < 8; i++)
#pragma unroll
        for (int j = 0; j < 8; j++) acc[i][j] += bj[j];

    float inv[8];
#pragma unroll
    for (int i = 0; i < 8; i++) inv[i] = 1.0f;
    if (NORM) {
#pragma unroll
        for (int i = 0; i < 8; i++) {
            float ss = 0.f;
#pragma unroll
            for (int j = 0; j < 8; j++) ss += acc[i][j] * acc[i][j];
            ss += __shfl_xor_sync(0xffffffffu, ss, 1);
            ss += __shfl_xor_sync(0xffffffffu, ss, 2);
            ss += __shfl_xor_sync(0xffffffffu, ss, 4);
            ss += __shfl_xor_sync(0xffffffffu, ss, 8);
            inv[i] = 1.0f / fmaxf(sqrtf(ss), 1e-12f);
        }
    }

    float4* O4 = (float4*)outp;
#pragma unroll
    for (int i = 0; i < 8; i++) {
        int grow = row0 + tr * 8 + i;
        if (grow < NN) {
            float4 o0 = make_float4(acc[i][0] * inv[i], acc[i][1] * inv[i],
                                    acc[i][2] * inv[i], acc[i][3] * inv[i]);
            float4 o1 = make_float4(acc[i][4] * inv[i], acc[i][5] * inv[i],
                                    acc[i][6] * inv[i], acc[i][7] * inv[i]);
            O4[grow * 32 + tc]      = o0;
            O4[grow * 32 + 16 + tc] = o1;
        }
    }
}

// ---------------- global add pool ----------------
__global__ void pool_kernel(const float* __restrict__ h, const int* __restrict__ batch,
                            float* __restrict__ g) {
    int i = blockIdx.x * blockDim.x + threadIdx.x;
    if (i < NN * HH) {
        int node = i >> 7, c = i & 127;
        atomicAdd(&g[batch[node] * HH + c], h[i]);
    }
}

// ---------------- MLP head: one block per graph ----------------
__global__ void __launch_bounds__(128) mlp_head_kernel(
    const float* __restrict__ g,
    const float* __restrict__ W0, const float* __restrict__ b0,
    const float* __restrict__ W1, const float* __restrict__ b1,
    const float* __restrict__ hw, const float* __restrict__ hb,
    float* __restrict__ out) {
    __shared__ float sg[HH];
    __shared__ float st[HH];
    __shared__ float red[4];
    int b = blockIdx.x, t = threadIdx.x;
    sg[t] = g[b * HH + t];
    __syncthreads();
    float s = 0.f;
#pragma unroll 8
    for (int k = 0; k < HH; k++) s = fmaf(sg[k], W0[k * HH + t], s);
    s = fmaxf(s + b0[t], 0.f);
    st[t] = s;
    __syncthreads();
    float s2 = 0.f;
#pragma unroll 8
    for (int k = 0; k < HH; k++) s2 = fmaf(st[k], W1[k * HH + t], s2);
    s2 = fmaxf(s2 + b1[t], 0.f);
    float p = s2 * hw[t];
#pragma unroll
    for (int o = 16; o > 0; o >>= 1) p += __shfl_xor_sync(0xffffffffu, p, o);
    if ((t & 31) == 0) red[t >> 5] = p;
    __syncthreads();
    if (t == 0) out[b] = red[0] + red[1] + red[2] + red[3] + hb[0];
}

// ---------------- host launcher ----------------
extern "C" void kernel_launch(void* const* d_in, const int* in_sizes, int n_in,
                              void* d_out, int out_size) {
    const float* x     = (const float*)d_in[0];
    const int*   eic   = (const int*)d_in[1];
    const int*   eid   = (const int*)d_in[2];
    const int*   eit   = (const int*)d_in[3];
    const int*   batch = (const int*)d_in[4];
    const float *Wl[5], *bl[5], *Wr[5];
    for (int c = 0; c < 5; c++) {
        Wl[c] = (const float*)d_in[5 + 3 * c];
        bl[c] = (const float*)d_in[6 + 3 * c];
        Wr[c] = (const float*)d_in[7 + 3 * c];
    }
    const float* l0W = (const float*)d_in[20];
    const float* l0b = (const float*)d_in[21];
    const float* l1W = (const float*)d_in[22];
    const float* l1b = (const float*)d_in[23];
    const float* hW  = (const float*)d_in[24];
    const float* hb  = (const float*)d_in[25];

    float *h0, *h1, *agg, *invc, *g;
    int *rowptr, *cur, *ssrc;
    cudaGetSymbolAddress((void**)&h0, d_h0);
    cudaGetSymbolAddress((void**)&h1, d_h1);
    cudaGetSymbolAddress((void**)&agg, d_agg);
    cudaGetSymbolAddress((void**)&rowptr, d_rowptr);
    cudaGetSymbolAddress((void**)&cur, d_cur);
    cudaGetSymbolAddress((void**)&ssrc, d_ssrc);
    cudaGetSymbolAddress((void**)&invc, d_invc);
    cudaGetSymbolAddress((void**)&g, d_g);

    // build CSR for the 3 edge sets: 0=eic, 1=eid, 2=eit
    const int* esets[3] = {eic, eid, eit};
    for (int s = 0; s < 3; s++) {
        zero_int_kernel<<<(NN + 255) / 256, 256>>>(cur + s * NN, NN);
        hist_kernel<<<(EE + 255) / 256, 256>>>(esets[s] + EE, cur + s * NN);
        scan_kernel<<<1, 1024>>>(cur + s * NN, rowptr + s * (NN + 1), invc + s * NN);
        fill_kernel<<<(EE + 255) / 256, 256>>>(esets[s], esets[s] + EE,
                                               cur + s * NN, ssrc + (size_t)s * EE);
    }

    // 7 SAGE layers: {edge set, conv weights, normalize}
    const int   set_of[7]  = {1, 0, 0, 2, 1, 0, 0};
    const int   conv_of[7] = {0, 1, 1, 2, 3, 4, 4};
    const bool  norm_of[7] = {true, true, true, false, true, true, true};

    const int gemm_grid = (NN + 127) / 128;
    const float* cin = x;
    float* bufs[2] = {h0, h1};
    for (int l = 0; l < 7; l++) {
        int s = set_of[l], c = conv_of[l];
        gather_kernel<<<(NN * 32 + 255) / 256, 256>>>(
            cin, rowptr + s * (NN + 1), ssrc + (size_t)s * EE, invc + s * NN, agg);
        float* outp = bufs[l & 1];
        if (norm_of[l])
            sage_gemm<true><<<gemm_grid, 256>>>(agg, cin, Wl[c], Wr[c], bl[c], outp);
        else
            sage_gemm<false><<<gemm_grid, 256>>>(agg, cin, Wl[c], Wr[c], bl[c], outp);
        cin = outp;
    }

    // pool + MLP + head
    zero_float_kernel<<<(GG * HH + 255) / 256, 256>>>(g, GG * HH);
    pool_kernel<<<(NN * HH + 255) / 256, 256>>>(cin, batch, g);
    mlp_head_kernel<<<GG, 128>>>(g, l0W, l0b, l1W, l1b, hW, hb, (float*)d_out);
}

// round 4
// speedup vs baseline: 1.5365x; 1.5365x over previous
#include <cuda_runtime.h>
#include <cuda_bf16.h>
#include <mma.h>

using namespace nvcuda;
typedef __nv_bfloat16 bf16;

#define NN 50000
#define NPAD 50048
#define EE 600000
#define HH 128
#define GG 64
#define APAD 40
#define BPAD 136

// ---------------- static scratch ----------------
__device__ __align__(16) float d_h[NN * HH];        // current layer activations fp32
__device__ __align__(16) float d_tmp[NPAD * HH];    // raw gemm output (padded rows)
__device__ __align__(16) bf16  d_xhi[NN * HH];      // input split hi
__device__ __align__(16) bf16  d_xlo[NN * HH];      // input split lo
__device__ __align__(16) bf16  d_ahi[NN * HH];      // agg split hi
__device__ __align__(16) bf16  d_alo[NN * HH];      // agg split lo
__device__ __align__(16) bf16  d_Whi[5 * 256 * HH]; // [Wl;Wr] stacked, split hi
__device__ __align__(16) bf16  d_Wlo[5 * 256 * HH];
__device__ int   d_rowptr[3 * (NN + 1)];
__device__ int   d_cur[3 * NN];
__device__ int   d_ssrc[3 * EE];
__device__ float d_invc[3 * NN];
__device__ __align__(16) float d_g[GG * HH];

// ---------------- helpers ----------------
__device__ __forceinline__ void split4(float4 v, float4& hi, float4& lo,
                                       uint2& uh, uint2& ul) {
    bf16 hx = __float2bfloat16_rn(v.x), hy = __float2bfloat16_rn(v.y);
    bf16 hz = __float2bfloat16_rn(v.z), hw = __float2bfloat16_rn(v.w);
    hi = make_float4(__bfloat162float(hx), __bfloat162float(hy),
                     __bfloat162float(hz), __bfloat162float(hw));
    lo = make_float4(v.x - hi.x, v.y - hi.y, v.z - hi.z, v.w - hi.w);
    bf16 lx = __float2bfloat16_rn(lo.x), ly = __float2bfloat16_rn(lo.y);
    bf16 lz = __float2bfloat16_rn(lo.z), lw = __float2bfloat16_rn(lo.w);
    __nv_bfloat162 a = __halves2bfloat162(hx, hy);
    __nv_bfloat162 b = __halves2bfloat162(hz, hw);
    __nv_bfloat162 c = __halves2bfloat162(lx, ly);
    __nv_bfloat162 d = __halves2bfloat162(lz, lw);
    uh.x = *(unsigned int*)&a; uh.y = *(unsigned int*)&b;
    ul.x = *(unsigned int*)&c; ul.y = *(unsigned int*)&d;
}

// ---------------- small utility kernels ----------------
__global__ void zero_int_kernel(int* __restrict__ p, int n) {
    int i = blockIdx.x * blockDim.x + threadIdx.x;
    if (i < n) p[i] = 0;
}
__global__ void zero_float_kernel(float* __restrict__ p, int n) {
    int i = blockIdx.x * blockDim.x + threadIdx.x;
    if (i < n) p[i] = 0.0f;
}

// ---------------- CSR build (3 edge sets batched) ----------------
__global__ void hist3_kernel(const int* __restrict__ e0, const int* __restrict__ e1,
                             const int* __restrict__ e2, int* __restrict__ cnt) {
    int e = blockIdx.x * blockDim.x + threadIdx.x;
    if (e >= 3 * EE) return;
    int s = e / EE, le = e - s * EE;
    const int* dst = (s == 0 ? e0 : (s == 1 ? e1 : e2)) + EE;
    atomicAdd(&cnt[s * NN + dst[le]], 1);
}

__global__ void scan3_kernel(int* __restrict__ cntcur_all, int* __restrict__ rowptr_all,
                             float* __restrict__ invc_all) {
    int s = blockIdx.x;
    int* cntcur = cntcur_all + s * NN;
    int* rowptr = rowptr_all + s * (NN + 1);
    float* invc = invc_all + s * NN;
    __shared__ int wsum[32];
    __shared__ int sbase;
    int tid = threadIdx.x, lane = tid & 31, wid = tid >> 5;
    if (tid == 0) sbase = 0;
    __syncthreads();
    for (int start = 0; start < NN; start += 1024) {
        int i = start + tid;
        int v = (i < NN) ? cntcur[i] : 0;
        int xinc = v;
#pragma unroll
        for (int o = 1; o < 32; o <<= 1) {
            int y = __shfl_up_sync(0xffffffffu, xinc, o);
            if (lane >= o) xinc += y;
        }
        if (lane == 31) wsum[wid] = xinc;
        __syncthreads();
        if (wid == 0) {
            int wv = wsum[lane];
            int ws = wv;
#pragma unroll
            for (int o = 1; o < 32; o <<= 1) {
                int y = __shfl_up_sync(0xffffffffu, ws, o);
                if (lane >= o) ws += y;
            }
            wsum[lane] = ws - wv;
        }
        __syncthreads();
        int excl = xinc - v + wsum[wid] + sbase;
        if (i < NN) {
            rowptr[i] = excl;
            cntcur[i] = excl;
            invc[i]   = 1.0f / (float)((v > 0) ? v : 1);
        }
        __syncthreads();
        if (tid == 1023) sbase = excl + v;
        __syncthreads();
    }
    if (tid == 0) rowptr[NN] = sbase;
}

__global__ void fill3_kernel(const int* __restrict__ e0, const int* __restrict__ e1,
                             const int* __restrict__ e2,
                             int* __restrict__ cur, int* __restrict__ ssrc) {
    int e = blockIdx.x * blockDim.x + threadIdx.x;
    if (e >= 3 * EE) return;
    int s = e / EE, le = e - s * EE;
    const int* es = (s == 0 ? e0 : (s == 1 ? e1 : e2));
    int p = atomicAdd(&cur[s * NN + es[EE + le]], 1);
    ssrc[(size_t)s * EE + p] = es[le];
}

// ---------------- weight & input conversion ----------------
__global__ void convW_kernel(const float* __restrict__ Wl, const float* __restrict__ Wr,
                             bf16* __restrict__ oh, bf16* __restrict__ ol) {
    int idx = blockIdx.x * blockDim.x + threadIdx.x;   // 8192 float4s
    if (idx >= 256 * 32) return;
    int r = idx >> 5, q = idx & 31;
    const float* src = (r < 128) ? (Wl + r * HH) : (Wr + (r - 128) * HH);
    float4 v = ((const float4*)src)[q];
    float4 hi, lo; uint2 uh, ul;
    split4(v, hi, lo, uh, ul);
    *(uint2*)(oh + r * HH + q * 4) = uh;
    *(uint2*)(ol + r * HH + q * 4) = ul;
}

__global__ void convX_kernel(const float* __restrict__ x,
                             bf16* __restrict__ oh, bf16* __restrict__ ol) {
    int i = blockIdx.x * blockDim.x + threadIdx.x;     // N*32 float4s
    if (i >= NN * 32) return;
    float4 v = ((const float4*)x)[i];
    float4 hi, lo; uint2 uh, ul;
    split4(v, hi, lo, uh, ul);
    *(uint2*)(oh + i * 4) = uh;
    *(uint2*)(ol + i * 4) = ul;
}

// ---------------- mean-aggregate: warp/node gather -> bf16 hi/lo ----------
__global__ void __launch_bounds__(256) gather_kernel(
    const float* __restrict__ xin, const int* __restrict__ rowptr,
    const int* __restrict__ ssrc, const float* __restrict__ invc,
    bf16* __restrict__ ahi, bf16* __restrict__ alo) {
    int gw = (blockIdx.x * blockDim.x + threadIdx.x) >> 5;
    int lane = threadIdx.x & 31;
    if (gw >= NN) return;
    const float4* X = (const float4*)xin;
    int beg = rowptr[gw], end = rowptr[gw + 1];
    float4 acc = make_float4(0.f, 0.f, 0.f, 0.f);
    int e = beg;
    for (; e + 2 <= end; e += 2) {
        int s0 = ssrc[e], s1 = ssrc[e + 1];
        float4 v0 = X[s0 * 32 + lane];
        float4 v1 = X[s1 * 32 + lane];
        acc.x += v0.x + v1.x;
        acc.y += v0.y + v1.y;
        acc.z += v0.z + v1.z;
        acc.w += v0.w + v1.w;
    }
    if (e < end) {
        int s = ssrc[e];
        float4 v = X[s * 32 + lane];
        acc.x += v.x; acc.y += v.y; acc.z += v.z; acc.w += v.w;
    }
    float ic = invc[gw];
    float4 o = make_float4(acc.x * ic, acc.y * ic, acc.z * ic, acc.w * ic);
    float4 hi, lo; uint2 uh, ul;
    split4(o, hi, lo, uh, ul);
    *(uint2*)(ahi + (size_t)gw * HH + lane * 4) = uh;
    *(uint2*)(alo + (size_t)gw * HH + lane * 4) = ul;
}

// ---------------- tensor-core dual GEMM (bf16 split, fp32 acc) -----------
// out[r,:] = [agg|x][r,:] @ [Wl;Wr]   (K=256), raw (no bias/norm)
__global__ void __launch_bounds__(256, 2) gemm_tc(
    const bf16* __restrict__ Ah0, const bf16* __restrict__ Al0,
    const bf16* __restrict__ Ah1, const bf16* __restrict__ Al1,
    const bf16* __restrict__ Wh, const bf16* __restrict__ Wl_,
    float* __restrict__ outp) {
    __shared__ __align__(32) bf16 sAh[128 * APAD];
    __shared__ __align__(32) bf16 sAl[128 * APAD];
    __shared__ __align__(32) bf16 sBh[32 * BPAD];
    __shared__ __align__(32) bf16 sBl[32 * BPAD];

    const int tid = threadIdx.x;
    const int row0 = blockIdx.x * 128;
    const int warp = tid >> 5;
    const int wr = warp >> 1, wc = warp & 1;

    wmma::fragment<wmma::accumulator, 16, 16, 16, float> acc[2][4];
#pragma unroll
    for (int i = 0; i < 2; i++)
#pragma unroll
        for (int j = 0; j < 4; j++) wmma::fill_fragment(acc[i][j], 0.0f);

    const int ar = tid >> 1, ah = tid & 1;   // A stage: 2 threads/row
    const int br = tid >> 3, bs = tid & 7;   // B stage: 8 threads/row

    for (int kb = 0; kb < 8; kb++) {
        const bf16* Ahp = (kb < 4) ? Ah0 : Ah1;
        const bf16* Alp = (kb < 4) ? Al0 : Al1;
        const int koff = (kb & 3) * 32;
        uint4 vh0 = {0,0,0,0}, vh1 = {0,0,0,0}, vl0 = {0,0,0,0}, vl1 = {0,0,0,0};
        int grow = row0 + ar;
        if (grow < NN) {
            const uint4* ph = (const uint4*)(Ahp + (size_t)grow * HH + koff);
            const uint4* pl = (const uint4*)(Alp + (size_t)grow * HH + koff);
            vh0 = ph[ah * 2]; vh1 = ph[ah * 2 + 1];
            vl0 = pl[ah * 2]; vl1 = pl[ah * 2 + 1];
        }
        const uint4* pBh = (const uint4*)(Wh  + (size_t)(kb * 32 + br) * HH + bs * 16);
        const uint4* pBl = (const uint4*)(Wl_ + (size_t)(kb * 32 + br) * HH + bs * 16);
        uint4 wh0 = pBh[0], wh1 = pBh[1];
        uint4 wl0 = pBl[0], wl1 = pBl[1];
        __syncthreads();
        *(uint4*)&sAh[ar * APAD + ah * 16]     = vh0;
        *(uint4*)&sAh[ar * APAD + ah * 16 + 8] = vh1;
        *(uint4*)&sAl[ar * APAD + ah * 16]     = vl0;
        *(uint4*)&sAl[ar * APAD + ah * 16 + 8] = vl1;
        *(uint4*)&sBh[br * BPAD + bs * 16]     = wh0;
        *(uint4*)&sBh[br * BPAD + bs * 16 + 8] = wh1;
        *(uint4*)&sBl[br * BPAD + bs * 16]     = wl0;
        *(uint4*)&sBl[br * BPAD + bs * 16 + 8] = wl1;
        __syncthreads();
#pragma unroll
        for (int ks = 0; ks < 32; ks += 16) {
            wmma::fragment<wmma::matrix_a, 16, 16, 16, bf16, wmma::row_major> fah[2], fal[2];
#pragma unroll
            for (int i = 0; i < 2; i++) {
                wmma::load_matrix_sync(fah[i], &sAh[(wr * 32 + i * 16) * APAD + ks], APAD);
                wmma::load_matrix_sync(fal[i], &sAl[(wr * 32 + i * 16) * APAD + ks], APAD);
            }
#pragma unroll
            for (int j = 0; j < 4; j++) {
                wmma::fragment<wmma::matrix_b, 16, 16, 16, bf16, wmma::row_major> fbh, fbl;
                wmma::load_matrix_sync(fbh, &sBh[ks * BPAD + wc * 64 + j * 16], BPAD);
                wmma::load_matrix_sync(fbl, &sBl[ks * BPAD + wc * 64 + j * 16], BPAD);
#pragma unroll
                for (int i = 0; i < 2; i++) {
                    wmma::mma_sync(acc[i][j], fah[i], fbh, acc[i][j]);
                    wmma::mma_sync(acc[i][j], fah[i], fbl, acc[i][j]);
                    wmma::mma_sync(acc[i][j], fal[i], fbh, acc[i][j]);
                }
            }
        }
    }
#pragma unroll
    for (int i = 0; i < 2; i++)
#pragma unroll
        for (int j = 0; j < 4; j++) {
            size_t off = (size_t)(row0 + wr * 32 + i * 16) * HH + wc * 64 + j * 16;
            wmma::store_matrix_sync(&d_tmp[0] + off, acc[i][j], HH, wmma::mem_row_major);
        }
    (void)outp;
}

// ---------------- epilogue: bias + optional L2 norm + split ---------------
__global__ void __launch_bounds__(256) norm_convert(
    const float* __restrict__ tmp, const float* __restrict__ bias, int donorm,
    float* __restrict__ h, bf16* __restrict__ hhi, bf16* __restrict__ hlo) {
    int w = (blockIdx.x * blockDim.x + threadIdx.x) >> 5;
    int lane = threadIdx.x & 31;
    if (w >= NN) return;
    float4 v = ((const float4*)tmp)[(size_t)w * 32 + lane];
    float4 b = ((const float4*)bias)[lane];
    v.x += b.x; v.y += b.y; v.z += b.z; v.w += b.w;
    if (donorm) {
        float ss = v.x * v.x + v.y * v.y + v.z * v.z + v.w * v.w;
        ss += __shfl_xor_sync(0xffffffffu, ss, 1);
        ss += __shfl_xor_sync(0xffffffffu, ss, 2);
        ss += __shfl_xor_sync(0xffffffffu, ss, 4);
        ss += __shfl_xor_sync(0xffffffffu, ss, 8);
        ss += __shfl_xor_sync(0xffffffffu, ss, 16);
        float inv = 1.0f / fmaxf(sqrtf(ss), 1e-12f);
        v.x *= inv; v.y *= inv; v.z *= inv; v.w *= inv;
    }
    ((float4*)h)[(size_t)w * 32 + lane] = v;
    float4 hi, lo; uint2 uh, ul;
    split4(v, hi, lo, uh, ul);
    *(uint2*)(hhi + (size_t)w * HH + lane * 4) = uh;
    *(uint2*)(hlo + (size_t)w * HH + lane * 4) = ul;
}

// ---------------- global add pool (sorted-run accumulation) ---------------
__global__ void __launch_bounds__(128) pool_kernel(
    const float* __restrict__ h, const int* __restrict__ batch,
    float* __restrict__ g) {
    int c = threadIdx.x;
    int n0 = blockIdx.x * 128;
    int nend = min(n0 + 128, NN);
    float local = 0.f;
    int gprev = batch[n0];
    for (int n = n0; n < nend; n++) {
        int gb = batch[n];
        if (gb != gprev) {
            atomicAdd(&g[gprev * HH + c], local);
            local = 0.f; gprev = gb;
        }
        local += h[(size_t)n * HH + c];
    }
    atomicAdd(&g[gprev * HH + c], local);
}

// ---------------- MLP head ----------------
__global__ void __launch_bounds__(128) mlp_head_kernel(
    const float* __restrict__ g,
    const float* __restrict__ W0, const float* __restrict__ b0,
    const float* __restrict__ W1, const float* __restrict__ b1,
    const float* __restrict__ hw, const float* __restrict__ hb,
    float* __restrict__ out) {
    __shared__ float sg[HH];
    __shared__ float st[HH];
    __shared__ float red[4];
    int b = blockIdx.x, t = threadIdx.x;
    sg[t] = g[b * HH + t];
    __syncthreads();
    float s = 0.f;
#pragma unroll 8
    for (int k = 0; k < HH; k++) s = fmaf(sg[k], W0[k * HH + t], s);
    s = fmaxf(s + b0[t], 0.f);
    st[t] = s;
    __syncthreads();
    float s2 = 0.f;
#pragma unroll 8
    for (int k = 0; k < HH; k++) s2 = fmaf(st[k], W1[k * HH + t], s2);
    s2 = fmaxf(s2 + b1[t], 0.f);
    float p = s2 * hw[t];
#pragma unroll
    for (int o = 16; o > 0; o >>= 1) p += __shfl_xor_sync(0xffffffffu, p, o);
    if ((t & 31) == 0) red[t >> 5] = p;
    __syncthreads();
    if (t == 0) out[b] = red[0] + red[1] + red[2] + red[3] + hb[0];
}

// ---------------- host launcher ----------------
extern "C" void kernel_launch(void* const* d_in, const int* in_sizes, int n_in,
                              void* d_out, int out_size) {
    const float* x     = (const float*)d_in[0];
    const int*   eic   = (const int*)d_in[1];
    const int*   eid   = (const int*)d_in[2];
    const int*   eit   = (const int*)d_in[3];
    const int*   batch = (const int*)d_in[4];
    const float *Wl[5], *bl[5], *Wr[5];
    for (int c = 0; c < 5; c++) {
        Wl[c] = (const float*)d_in[5 + 3 * c];
        bl[c] = (const float*)d_in[6 + 3 * c];
        Wr[c] = (const float*)d_in[7 + 3 * c];
    }
    const float* l0W = (const float*)d_in[20];
    const float* l0b = (const float*)d_in[21];
    const float* l1W = (const float*)d_in[22];
    const float* l1b = (const float*)d_in[23];
    const float* hW  = (const float*)d_in[24];
    const float* hb  = (const float*)d_in[25];

    float *h, *tmp, *invc, *g;
    bf16 *xhi, *xlo, *ahi, *alo, *Whi, *Wlo;
    int *rowptr, *cur, *ssrc;
    cudaGetSymbolAddress((void**)&h, d_h);
    cudaGetSymbolAddress((void**)&tmp, d_tmp);
    cudaGetSymbolAddress((void**)&xhi, d_xhi);
    cudaGetSymbolAddress((void**)&xlo, d_xlo);
    cudaGetSymbolAddress((void**)&ahi, d_ahi);
    cudaGetSymbolAddress((void**)&alo, d_alo);
    cudaGetSymbolAddress((void**)&Whi, d_Whi);
    cudaGetSymbolAddress((void**)&Wlo, d_Wlo);
    cudaGetSymbolAddress((void**)&rowptr, d_rowptr);
    cudaGetSymbolAddress((void**)&cur, d_cur);
    cudaGetSymbolAddress((void**)&ssrc, d_ssrc);
    cudaGetSymbolAddress((void**)&invc, d_invc);
    cudaGetSymbolAddress((void**)&g, d_g);

    // CSR build for 3 edge sets (batched)
    zero_int_kernel<<<(3 * NN + 255) / 256, 256>>>(cur, 3 * NN);
    hist3_kernel<<<(3 * EE + 255) / 256, 256>>>(eic, eid, eit, cur);
    scan3_kernel<<<3, 1024>>>(cur, rowptr, invc);
    fill3_kernel<<<(3 * EE + 255) / 256, 256>>>(eic, eid, eit, cur, ssrc);

    // weight + input conversion to bf16 hi/lo
    for (int c = 0; c < 5; c++)
        convW_kernel<<<32, 256>>>(Wl[c], Wr[c], Whi + c * 256 * HH, Wlo + c * 256 * HH);
    convX_kernel<<<(NN * 32 + 255) / 256, 256>>>(x, xhi, xlo);

    // 7 SAGE layers
    const int  set_of[7]  = {1, 0, 0, 2, 1, 0, 0};
    const int  conv_of[7] = {0, 1, 1, 2, 3, 4, 4};
    const int  norm_of[7] = {1, 1, 1, 0, 1, 1, 1};

    const int gemm_grid = (NN + 127) / 128;
    const float* cin = x;
    for (int l = 0; l < 7; l++) {
        int s = set_of[l], c = conv_of[l];
        gather_kernel<<<(NN * 32 + 255) / 256, 256>>>(
            cin, rowptr + s * (NN + 1), ssrc + (size_t)s * EE, invc + s * NN,
            ahi, alo);
        gemm_tc<<<gemm_grid, 256>>>(ahi, alo, xhi, xlo,
                                    Whi + c * 256 * HH, Wlo + c * 256 * HH, tmp);
        norm_convert<<<(NN * 32 + 255) / 256, 256>>>(tmp, bl[c], norm_of[l],
                                                     h, xhi, xlo);
        cin = h;
    }

    // pool + MLP + head
    zero_float_kernel<<<(GG * HH + 255) / 256, 256>>>(g, GG * HH);
    pool_kernel<<<(NN + 127) / 128, 128>>>(cin, batch, g);
    mlp_head_kernel<<<GG, 128>>>(g, l0W, l0b, l1W, l1b, hW, hb, (float*)d_out);
}

// round 12
// speedup vs baseline: 1.5388x; 1.0014x over previous
#include <cstdint>
#include <cuda_runtime.h>
#include <cuda_bf16.h>
#include <mma.h>

using namespace nvcuda;
typedef __nv_bfloat16 bf16;

#define NN 50000
#define EE 600000
#define HH 128
#define GG 64
#define APAD 40
#define BPAD 136
#define CP   136          // epilogue tile pitch (floats), multiple of 8
#define NCHUNK 196        // ceil(NN/256)

// ---------------- static scratch ----------------
__device__ __align__(16) float d_h[NN * HH];       // fp32 activations
__device__ __align__(16) bf16  d_xhi[NN * HH];     // activation split hi
__device__ __align__(16) bf16  d_xlo[NN * HH];     // activation split lo
__device__ __align__(16) bf16  d_ahi[NN * HH];     // agg split hi
__device__ __align__(16) bf16  d_alo[NN * HH];     // agg split lo
__device__ __align__(16) bf16  d_Whi[5 * 256 * HH];// [Wl;Wr] stacked [k][n], hi
__device__ __align__(16) bf16  d_Wlo[5 * 256 * HH];
__device__ int   d_rowptr[3 * (NN + 1)];
__device__ int   d_cur[3 * NN];
__device__ int   d_csum[3 * NCHUNK];
__device__ int   d_ssrc[3 * EE];
__device__ float d_invc[3 * NN];
__device__ __align__(16) float d_g[GG * HH];

// ---------------- split helper ----------------
__device__ __forceinline__ void split4(float4 v, uint2& uh, uint2& ul) {
    bf16 hx = __float2bfloat16_rn(v.x), hy = __float2bfloat16_rn(v.y);
    bf16 hz = __float2bfloat16_rn(v.z), hw = __float2bfloat16_rn(v.w);
    bf16 lx = __float2bfloat16_rn(v.x - __bfloat162float(hx));
    bf16 ly = __float2bfloat16_rn(v.y - __bfloat162float(hy));
    bf16 lz = __float2bfloat16_rn(v.z - __bfloat162float(hz));
    bf16 lw = __float2bfloat16_rn(v.w - __bfloat162float(hw));
    __nv_bfloat162 a = __halves2bfloat162(hx, hy);
    __nv_bfloat162 b = __halves2bfloat162(hz, hw);
    __nv_bfloat162 c = __halves2bfloat162(lx, ly);
    __nv_bfloat162 d = __halves2bfloat162(lz, lw);
    uh.x = *(unsigned int*)&a; uh.y = *(unsigned int*)&b;
    ul.x = *(unsigned int*)&c; ul.y = *(unsigned int*)&d;
}

// ---------------- utility ----------------
__global__ void zero_int_kernel(int* __restrict__ p, int n) {
    int i = blockIdx.x * blockDim.x + threadIdx.x;
    if (i < n) p[i] = 0;
}
__global__ void zero_float_kernel(float* __restrict__ p, int n) {
    int i = blockIdx.x * blockDim.x + threadIdx.x;
    if (i < n) p[i] = 0.0f;
}

// ---------------- CSR build ----------------
__global__ void hist3_kernel(const int* __restrict__ e0, const int* __restrict__ e1,
                             const int* __restrict__ e2, int* __restrict__ cnt) {
    int e = blockIdx.x * blockDim.x + threadIdx.x;
    if (e >= 3 * EE) return;
    int s = e / EE, le = e - s * EE;
    const int* dst = (s == 0 ? e0 : (s == 1 ? e1 : e2)) + EE;
    atomicAdd(&cnt[s * NN + dst[le]], 1);
}

// phase 1: per-256-chunk sums
__global__ void chunksum_kernel(const int* __restrict__ cur, int* __restrict__ csum) {
    int blk = blockIdx.x, s = blk / NCHUNK, c = blk - s * NCHUNK;
    int tid = threadIdx.x;
    int i = c * 256 + tid;
    int v = (i < NN) ? cur[s * NN + i] : 0;
#pragma unroll
    for (int o = 16; o > 0; o >>= 1) v += __shfl_down_sync(0xffffffffu, v, o);
    __shared__ int ws[8];
    if ((tid & 31) == 0) ws[tid >> 5] = v;
    __syncthreads();
    if (tid == 0) {
        int t = 0;
#pragma unroll
        for (int k = 0; k < 8; k++) t += ws[k];
        csum[s * NCHUNK + c] = t;
    }
}

// phase 2: exclusive scan of NCHUNK sums per set (3 blocks)
__global__ void chunkscan_kernel(int* __restrict__ csum, int* __restrict__ rowptr_all) {
    int s = blockIdx.x, t = threadIdx.x;
    __shared__ int sh[256];
    int v = (t < NCHUNK) ? csum[s * NCHUNK + t] : 0;
    sh[t] = v;
    __syncthreads();
    for (int o = 1; o < 256; o <<= 1) {
        int x = (t >= o) ? sh[t - o] : 0;
        __syncthreads();
        sh[t] += x;
        __syncthreads();
    }
    if (t < NCHUNK) csum[s * NCHUNK + t] = sh[t] - v;
    if (t == NCHUNK - 1) rowptr_all[s * (NN + 1) + NN] = sh[t];
}

// phase 3: block-local exclusive scan + chunk base -> rowptr/cur/invc
__global__ void applyscan_kernel(const int* __restrict__ csum, int* __restrict__ cur,
                                 int* __restrict__ rowptr_all, float* __restrict__ invc_all) {
    int blk = blockIdx.x, s = blk / NCHUNK, c = blk - s * NCHUNK;
    int tid = threadIdx.x, lane = tid & 31, w = tid >> 5;
    int i = c * 256 + tid;
    int v = (i < NN) ? cur[s * NN + i] : 0;
    int x = v;
#pragma unroll
    for (int o = 1; o < 32; o <<= 1) {
        int y = __shfl_up_sync(0xffffffffu, x, o);
        if (lane >= o) x += y;
    }
    __shared__ int wsum[8];
    __shared__ int wexcl[8];
    if (lane == 31) wsum[w] = x;
    __syncthreads();
    if (tid == 0) {
        int run = 0;
#pragma unroll
        for (int k = 0; k < 8; k++) { wexcl[k] = run; run += wsum[k]; }
    }
    __syncthreads();
    int excl = x - v + wexcl[w] + csum[s * NCHUNK + c];
    if (i < NN) {
        rowptr_all[s * (NN + 1) + i] = excl;
        cur[s * NN + i] = excl;
        invc_all[s * NN + i] = 1.0f / (float)((v > 0) ? v : 1);
    }
}

__global__ void fill3_kernel(const int* __restrict__ e0, const int* __restrict__ e1,
                             const int* __restrict__ e2,
                             int* __restrict__ cur, int* __restrict__ ssrc) {
    int e = blockIdx.x * blockDim.x + threadIdx.x;
    if (e >= 3 * EE) return;
    int s = e / EE, le = e - s * EE;
    const int* es = (s == 0 ? e0 : (s == 1 ? e1 : e2));
    int p = atomicAdd(&cur[s * NN + es[EE + le]], 1);
    ssrc[(size_t)s * EE + p] = es[le];
}

// ---------------- weight stack + split: [Wl;Wr] as [k=256][n=128] ----------
__global__ void convW_kernel(const float* __restrict__ Wl, const float* __restrict__ Wr,
                             bf16* __restrict__ oh, bf16* __restrict__ ol) {
    int idx = blockIdx.x * blockDim.x + threadIdx.x;
    if (idx >= 256 * 32) return;
    int r = idx >> 5, q = idx & 31;
    const float* src = (r < 128) ? (Wl + r * HH) : (Wr + (r - 128) * HH);
    float4 v = ((const float4*)src)[q];
    uint2 uh, ul;
    split4(v, uh, ul);
    *(uint2*)(oh + r * HH + q * 4) = uh;
    *(uint2*)(ol + r * HH + q * 4) = ul;
}

__global__ void convX_kernel(const float* __restrict__ x,
                             bf16* __restrict__ oh, bf16* __restrict__ ol) {
    int i = blockIdx.x * blockDim.x + threadIdx.x;
    if (i >= NN * 32) return;
    float4 v = ((const float4*)x)[i];
    uint2 uh, ul;
    split4(v, uh, ul);
    *(uint2*)(oh + (size_t)i * 4) = uh;
    *(uint2*)(ol + (size_t)i * 4) = ul;
}

// ---------------- mean-aggregate (warp/node gather) -> bf16 hi/lo ---------
__global__ void __launch_bounds__(256) gather_kernel(
    const float* __restrict__ xin, const int* __restrict__ rowptr,
    const int* __restrict__ ssrc, const float* __restrict__ invc,
    bf16* __restrict__ ahi, bf16* __restrict__ alo) {
    int gw = (blockIdx.x * blockDim.x + threadIdx.x) >> 5;
    int lane = threadIdx.x & 31;
    if (gw >= NN) return;
    const float4* X = (const float4*)xin;
    int beg = rowptr[gw], end = rowptr[gw + 1];
    float4 acc = make_float4(0.f, 0.f, 0.f, 0.f);
    int e = beg;
    for (; e + 2 <= end; e += 2) {
        int s0 = ssrc[e], s1 = ssrc[e + 1];
        float4 v0 = X[s0 * 32 + lane];
        float4 v1 = X[s1 * 32 + lane];
        acc.x += v0.x + v1.x;
        acc.y += v0.y + v1.y;
        acc.z += v0.z + v1.z;
        acc.w += v0.w + v1.w;
    }
    if (e < end) {
        int s = ssrc[e];
        float4 v = X[s * 32 + lane];
        acc.x += v.x; acc.y += v.y; acc.z += v.z; acc.w += v.w;
    }
    float ic = invc[gw];
    float4 o = make_float4(acc.x * ic, acc.y * ic, acc.z * ic, acc.w * ic);
    uint2 uh, ul;
    split4(o, uh, ul);
    *(uint2*)(ahi + (size_t)gw * HH + lane * 4) = uh;
    *(uint2*)(alo + (size_t)gw * HH + lane * 4) = ul;
}

// ---------------- fused wmma dual GEMM + bias + L2-norm + split -----------
// out[r,:] = [agg|x][r,:] @ [Wl;Wr]  (K=256, 3 split products), then
// bias + optional normalize + fp32/bf16-split writeback, all in one kernel.
__global__ void __launch_bounds__(256) gemm_fused(
    const bf16* __restrict__ Ah0, const bf16* __restrict__ Al0,
    const bf16* __restrict__ Ah1, const bf16* __restrict__ Al1,
    const bf16* __restrict__ Wh, const bf16* __restrict__ Wl_,
    const float* __restrict__ bias, int donorm,
    float* __restrict__ hout, bf16* __restrict__ ohi, bf16* __restrict__ olo) {
    extern __shared__ __align__(16) char dsm[];
    float* sbias = (float*)dsm;                 // 512 B
    bf16* sAh = (bf16*)(dsm + 1024);            // 128 x APAD
    bf16* sAl = sAh + 128 * APAD;
    bf16* sBh = sAl + 128 * APAD;               // 32 x BPAD
    bf16* sBl = sBh + 32 * BPAD;
    float* tile = (float*)(dsm + 1024);         // union: 128 x CP fp32

    const int tid = threadIdx.x;
    const int warp = tid >> 5, lane = tid & 31;
    const int wr = warp >> 1, wc = warp & 1;
    const int row0 = blockIdx.x * 128;

    if (tid < 128) sbias[tid] = bias[tid];

    wmma::fragment<wmma::accumulator, 16, 16, 16, float> acc[2][4];
#pragma unroll
    for (int i = 0; i < 2; i++)
#pragma unroll
        for (int j = 0; j < 4; j++) wmma::fill_fragment(acc[i][j], 0.0f);

    const int ar = tid >> 1, ahf = tid & 1;   // A stage: 2 threads/row
    const int br = tid >> 3, bs = tid & 7;    // B stage: 8 threads/row

    for (int kb = 0; kb < 8; kb++) {
        const bf16* Ahp = (kb < 4) ? Ah0 : Ah1;
        const bf16* Alp = (kb < 4) ? Al0 : Al1;
        const int koff = (kb & 3) * 32;
        uint4 vh0 = {0,0,0,0}, vh1 = {0,0,0,0}, vl0 = {0,0,0,0}, vl1 = {0,0,0,0};
        int grow = row0 + ar;
        if (grow < NN) {
            const uint4* ph = (const uint4*)(Ahp + (size_t)grow * HH + koff);
            const uint4* pl = (const uint4*)(Alp + (size_t)grow * HH + koff);
            vh0 = ph[ahf * 2]; vh1 = ph[ahf * 2 + 1];
            vl0 = pl[ahf * 2]; vl1 = pl[ahf * 2 + 1];
        }
        const uint4* pBh = (const uint4*)(Wh  + (size_t)(kb * 32 + br) * HH + bs * 16);
        const uint4* pBl = (const uint4*)(Wl_ + (size_t)(kb * 32 + br) * HH + bs * 16);
        uint4 wh0 = pBh[0], wh1 = pBh[1];
        uint4 wl0 = pBl[0], wl1 = pBl[1];
        __syncthreads();
        *(uint4*)&sAh[ar * APAD + ahf * 16]     = vh0;
        *(uint4*)&sAh[ar * APAD + ahf * 16 + 8] = vh1;
        *(uint4*)&sAl[ar * APAD + ahf * 16]     = vl0;
        *(uint4*)&sAl[ar * APAD + ahf * 16 + 8] = vl1;
        *(uint4*)&sBh[br * BPAD + bs * 16]     = wh0;
        *(uint4*)&sBh[br * BPAD + bs * 16 + 8] = wh1;
        *(uint4*)&sBl[br * BPAD + bs * 16]     = wl0;
        *(uint4*)&sBl[br * BPAD + bs * 16 + 8] = wl1;
        __syncthreads();
#pragma unroll
        for (int ks = 0; ks < 32; ks += 16) {
            wmma::fragment<wmma::matrix_a, 16, 16, 16, bf16, wmma::row_major> fah[2], fal[2];
#pragma unroll
            for (int i = 0; i < 2; i++) {
                wmma::load_matrix_sync(fah[i], &sAh[(wr * 32 + i * 16) * APAD + ks], APAD);
                wmma::load_matrix_sync(fal[i], &sAl[(wr * 32 + i * 16) * APAD + ks], APAD);
            }
#pragma unroll
            for (int j = 0; j < 4; j++) {
                wmma::fragment<wmma::matrix_b, 16, 16, 16, bf16, wmma::row_major> fbh, fbl;
                wmma::load_matrix_sync(fbh, &sBh[ks * BPAD + wc * 64 + j * 16], BPAD);
                wmma::load_matrix_sync(fbl, &sBl[ks * BPAD + wc * 64 + j * 16], BPAD);
#pragma unroll
                for (int i = 0; i < 2; i++) {
                    wmma::mma_sync(acc[i][j], fah[i], fbh, acc[i][j]);
                    wmma::mma_sync(acc[i][j], fah[i], fbl, acc[i][j]);
                    wmma::mma_sync(acc[i][j], fal[i], fbh, acc[i][j]);
                }
            }
        }
    }

    // ---- epilogue: dump accumulators to smem tile, bias+norm, writeback ----
    __syncthreads();   // A/B staging buffers dead; tile aliases them
#pragma unroll
    for (int i = 0; i < 2; i++)
#pragma unroll
        for (int j = 0; j < 4; j++)
            wmma::store_matrix_sync(&tile[(wr * 32 + i * 16) * CP + wc * 64 + j * 16],
                                    acc[i][j], CP, wmma::mem_row_major);
    __syncthreads();

    float4 bb = *(float4*)&sbias[lane * 4];
    int r0 = warp * 16;
#pragma unroll 2
    for (int rr = 0; rr < 16; rr++) {
        int r = r0 + rr;
        int grow = row0 + r;
        float4 v = *(float4*)&tile[r * CP + lane * 4];
        v.x += bb.x; v.y += bb.y; v.z += bb.z; v.w += bb.w;
        float inv = 1.0f;
        if (donorm) {
            float ss = v.x * v.x + v.y * v.y + v.z * v.z + v.w * v.w;
            ss += __shfl_xor_sync(0xffffffffu, ss, 1);
            ss += __shfl_xor_sync(0xffffffffu, ss, 2);
            ss += __shfl_xor_sync(0xffffffffu, ss, 4);
            ss += __shfl_xor_sync(0xffffffffu, ss, 8);
            ss += __shfl_xor_sync(0xffffffffu, ss, 16);
            inv = 1.0f / fmaxf(sqrtf(ss), 1e-12f);
        }
        if (grow < NN) {
            v.x *= inv; v.y *= inv; v.z *= inv; v.w *= inv;
            size_t off = (size_t)grow * HH + lane * 4;
            *(float4*)(hout + off) = v;
            uint2 uh, ul;
            split4(v, uh, ul);
            *(uint2*)(ohi + off) = uh;
            *(uint2*)(olo + off) = ul;
        }
    }
}

// ---------------- global add pool (sorted-run accumulation) ---------------
__global__ void __launch_bounds__(128) pool_kernel(
    const float* __restrict__ h, const int* __restrict__ batch,
    float* __restrict__ g) {
    int c = threadIdx.x;
    int n0 = blockIdx.x * 128;
    int nend = min(n0 + 128, NN);
    float local = 0.f;
    int gprev = batch[n0];
    for (int n = n0; n < nend; n++) {
        int gb = batch[n];
        if (gb != gprev) {
            atomicAdd(&g[gprev * HH + c], local);
            local = 0.f; gprev = gb;
        }
        local += h[(size_t)n * HH + c];
    }
    atomicAdd(&g[gprev * HH + c], local);
}

// ---------------- MLP head ----------------
__global__ void __launch_bounds__(128) mlp_head_kernel(
    const float* __restrict__ g,
    const float* __restrict__ W0, const float* __restrict__ b0,
    const float* __restrict__ W1, const float* __restrict__ b1,
    const float* __restrict__ hw, const float* __restrict__ hb,
    float* __restrict__ out) {
    __shared__ float sg[HH];
    __shared__ float st[HH];
    __shared__ float red[4];
    int b = blockIdx.x, t = threadIdx.x;
    sg[t] = g[b * HH + t];
    __syncthreads();
    float s = 0.f;
#pragma unroll 8
    for (int k = 0; k < HH; k++) s = fmaf(sg[k], W0[k * HH + t], s);
    s = fmaxf(s + b0[t], 0.f);
    st[t] = s;
    __syncthreads();
    float s2 = 0.f;
#pragma unroll 8
    for (int k = 0; k < HH; k++) s2 = fmaf(st[k], W1[k * HH + t], s2);
    s2 = fmaxf(s2 + b1[t], 0.f);
    float p = s2 * hw[t];
#pragma unroll
    for (int o = 16; o > 0; o >>= 1) p += __shfl_xor_sync(0xffffffffu, p, o);
    if ((t & 31) == 0) red[t >> 5] = p;
    __syncthreads();
    if (t == 0) out[b] = red[0] + red[1] + red[2] + red[3] + hb[0];
}

// ---------------- host launcher ----------------
extern "C" void kernel_launch(void* const* d_in, const int* in_sizes, int n_in,
                              void* d_out, int out_size) {
    const float* x     = (const float*)d_in[0];
    const int*   eic   = (const int*)d_in[1];
    const int*   eid   = (const int*)d_in[2];
    const int*   eit   = (const int*)d_in[3];
    const int*   batch = (const int*)d_in[4];
    const float *Wl[5], *bl[5], *Wr[5];
    for (int c = 0; c < 5; c++) {
        Wl[c] = (const float*)d_in[5 + 3 * c];
        bl[c] = (const float*)d_in[6 + 3 * c];
        Wr[c] = (const float*)d_in[7 + 3 * c];
    }
    const float* l0W = (const float*)d_in[20];
    const float* l0b = (const float*)d_in[21];
    const float* l1W = (const float*)d_in[22];
    const float* l1b = (const float*)d_in[23];
    const float* hW  = (const float*)d_in[24];
    const float* hb  = (const float*)d_in[25];

    float *h, *invc, *g;
    bf16 *xhi, *xlo, *ahi, *alo, *Whi, *Wlo;
    int *rowptr, *cur, *csum, *ssrc;
    cudaGetSymbolAddress((void**)&h, d_h);
    cudaGetSymbolAddress((void**)&xhi, d_xhi);
    cudaGetSymbolAddress((void**)&xlo, d_xlo);
    cudaGetSymbolAddress((void**)&ahi, d_ahi);
    cudaGetSymbolAddress((void**)&alo, d_alo);
    cudaGetSymbolAddress((void**)&Whi, d_Whi);
    cudaGetSymbolAddress((void**)&Wlo, d_Wlo);
    cudaGetSymbolAddress((void**)&rowptr, d_rowptr);
    cudaGetSymbolAddress((void**)&cur, d_cur);
    cudaGetSymbolAddress((void**)&csum, d_csum);
    cudaGetSymbolAddress((void**)&ssrc, d_ssrc);
    cudaGetSymbolAddress((void**)&invc, d_invc);
    cudaGetSymbolAddress((void**)&g, d_g);

    // dynamic smem: 1024 hdr + max(staging 37.9KB, tile 128*CP*4 = 69.6KB)
    const int SMEM_BYTES = 1024 + 128 * CP * 4;
    cudaFuncSetAttribute(gemm_fused, cudaFuncAttributeMaxDynamicSharedMemorySize,
                         SMEM_BYTES);

    // CSR build (3 edge sets, batched; multi-block scan)
    zero_int_kernel<<<(3 * NN + 255) / 256, 256>>>(cur, 3 * NN);
    hist3_kernel<<<(3 * EE + 255) / 256, 256>>>(eic, eid, eit, cur);
    chunksum_kernel<<<3 * NCHUNK, 256>>>(cur, csum);
    chunkscan_kernel<<<3, 256>>>(csum, rowptr);
    applyscan_kernel<<<3 * NCHUNK, 256>>>(csum, cur, rowptr, invc);
    fill3_kernel<<<(3 * EE + 255) / 256, 256>>>(eic, eid, eit, cur, ssrc);

    // weight stack+split, input split
    for (int c = 0; c < 5; c++)
        convW_kernel<<<32, 256>>>(Wl[c], Wr[c],
                                  Whi + c * 256 * HH, Wlo + c * 256 * HH);
    convX_kernel<<<(NN * 32 + 255) / 256, 256>>>(x, xhi, xlo);

    // 7 SAGE layers
    const int set_of[7]  = {1, 0, 0, 2, 1, 0, 0};
    const int conv_of[7] = {0, 1, 1, 2, 3, 4, 4};
    const int norm_of[7] = {1, 1, 1, 0, 1, 1, 1};

    const int gemm_grid = (NN + 127) / 128;
    const float* cin = x;
    for (int l = 0; l < 7; l++) {
        int s = set_of[l], c = conv_of[l];
        gather_kernel<<<(NN * 32 + 255) / 256, 256>>>(
            cin, rowptr + s * (NN + 1), ssrc + (size_t)s * EE, invc + s * NN,
            ahi, alo);
        gemm_fused<<<gemm_grid, 256, SMEM_BYTES>>>(
            ahi, alo, xhi, xlo,
            Whi + c * 256 * HH, Wlo + c * 256 * HH,
            bl[c], norm_of[l], h, xhi, xlo);
        cin = h;
    }

    // pool + MLP + head
    zero_float_kernel<<<(GG * HH + 255) / 256, 256>>>(g, GG * HH);
    pool_kernel<<<(NN + 127) / 128, 128>>>(cin, batch, g);
    mlp_head_kernel<<<GG, 128>>>(g, l0W, l0b, l1W, l1b, hW, hb, (float*)d_out);
}